// round 14
// baseline (speedup 1.0000x reference)
#include <cuda_runtime.h>
#include <cstdint>

typedef unsigned long long u64;
typedef unsigned int u32;

// ---------------- scratch ----------------
__device__ u64 g_act1[1024 * 196];                        // [b][14x14], bit c = channel
__device__ __align__(16) char g_act2s8[1024 * 3136];      // A: s8 +/-1, k = ch*49+p
__device__ __align__(16) char g_fc1s8[2048 * 3136];       // B: s8 +/-1 fc1 weights
__device__ __align__(16) u32 g_part[2][1024 * 1024];      // fc1 split-K partials, s16x2
__device__ u32 g_act3[1024 * 64];                         // [b][2048/32]
__device__ u64 g_w2[64 * 9];                              // conv2 w bits
__device__ u32 g_fc2b[10 * 64];                           // fc2 w bits

// ---------------- f32x2 helpers ----------------
__device__ __forceinline__ u64 pk2(float lo, float hi) {
    u64 r; asm("mov.b64 %0, {%1,%2};" : "=l"(r) : "f"(lo), "f"(hi)); return r;
}
__device__ __forceinline__ void upk2(float& lo, float& hi, u64 v) {
    asm("mov.b64 {%0,%1}, %2;" : "=f"(lo), "=f"(hi) : "l"(v));
}
__device__ __forceinline__ u64 fma2(u64 a, u64 b, u64 c) {
    u64 d; asm("fma.rn.f32x2 %0, %1, %2, %3;" : "=l"(d) : "l"(a), "l"(b), "l"(c)); return d;
}

// ---------------- mma / cp.async helpers ----------------
__device__ __forceinline__ void imma16832(int* d, const u32* a, const u32* b) {
    asm volatile("mma.sync.aligned.m16n8k32.row.col.s32.s8.s8.s32 "
                 "{%0,%1,%2,%3}, {%4,%5,%6,%7}, {%8,%9}, {%0,%1,%2,%3};"
                 : "+r"(d[0]), "+r"(d[1]), "+r"(d[2]), "+r"(d[3])
                 : "r"(a[0]), "r"(a[1]), "r"(a[2]), "r"(a[3]),
                   "r"(b[0]), "r"(b[1]));
}
__device__ __forceinline__ void cpa16(void* dst, const void* src) {
    u32 d = (u32)__cvta_generic_to_shared(dst);
    asm volatile("cp.async.cg.shared.global [%0], [%1], 16;" :: "r"(d), "l"(src));
}
#define CPA_COMMIT() asm volatile("cp.async.commit_group;" ::: "memory")
#define CPA_WAIT2()  asm volatile("cp.async.wait_group 2;" ::: "memory")
#define CPA_WAIT1()  asm volatile("cp.async.wait_group 1;" ::: "memory")
#define CPA_WAIT0()  asm volatile("cp.async.wait_group 0;" ::: "memory")

// =====================================================================
// k_front: conv1 (0..1023), fc1 weight sign->s8 (1024..2047), conv2-w pack (2048)
// =====================================================================
__global__ void __launch_bounds__(416, 3)
k_front(const float* __restrict__ x, const float* __restrict__ w1,
        const float* __restrict__ g1, const float* __restrict__ b1,
        const float* __restrict__ m1, const float* __restrict__ v1,
        const float* __restrict__ w2, const float* __restrict__ wfc1) {
    __shared__ __align__(16) char sraw[3328];
    int tid = threadIdx.x;
    int bid = blockIdx.x;

    if (bid < 1024) {
        float* ws = (float*)sraw;                       // [9][64]
        float* sm = (float*)(sraw + 2304);
        float* ss = (float*)(sraw + 2560);
        float* sb = (float*)(sraw + 2816);
        u64*  pmask = (u64*)(sraw + 3072);

        for (int i = tid; i < 576; i += 416) {
            int ch = i / 9, tap = i % 9;
            ws[tap * 64 + ch] = (w1[i] >= 0.f) ? 1.f : -1.f;
        }
        if (tid < 64) {
            sm[tid] = m1[tid];
            ss[tid] = g1[tid] * (1.0f / sqrtf(v1[tid] + 1e-5f));
            sb[tid] = b1[tid];
        }
        __syncthreads();
        if (tid == 0) {
            u64 mk = 0ull;
            for (int c = 0; c < 64; c++) if (ss[c] >= 0.f) mk |= 1ull << c;
            *pmask = mk;
        }
        __syncthreads();

        int b = bid;
        int t = tid < 392 ? tid : 391;
        int p = t >> 1, h = t & 1;
        int py = p / 14, px = p % 14;
        const float* xb = x + b * 784;

        u64 P[3][4];
        #pragma unroll
        for (int r = 0; r < 3; r++) {
            int yy = 2 * py - 1 + h + r; yy = yy < 0 ? 0 : (yy > 27 ? 27 : yy);
            #pragma unroll
            for (int c = 0; c < 4; c++) {
                int xx = 2 * px - 1 + c; xx = xx < 0 ? 0 : (xx > 27 ? 27 : xx);
                float v = xb[yy * 28 + xx];
                P[r][c] = pk2(v, v);
            }
        }

        const u64* wrow = (const u64*)ws;
        u64 wloc = 0ull;
        #pragma unroll 2
        for (int cp = 0; cp < 32; cp++) {
            u64 wt[9];
            #pragma unroll
            for (int k = 0; k < 9; k++) wt[k] = wrow[k * 32 + cp];
            u64 a0 = 0, a1 = 0;
            #pragma unroll
            for (int dy = 0; dy < 3; dy++) {
                #pragma unroll
                for (int dx = 0; dx < 3; dx++) {
                    int k = dy * 3 + dx;
                    a0 = fma2(wt[k], P[dy][dx],     a0);
                    a1 = fma2(wt[k], P[dy][dx + 1], a1);
                }
            }
            float f0l, f0h, f1l, f1h;
            upk2(f0l, f0h, a0); upk2(f1l, f1h, a1);
            int ch0 = 2 * cp, ch1 = ch0 + 1;
            {
                float mx = fmaxf(f0l, f1l), mn = fminf(f0l, f1l);
                float s = ss[ch0];
                float a = (s >= 0.f) ? mx : mn;
                if (((a - sm[ch0]) * s + sb[ch0]) >= 0.f) wloc |= 1ull << ch0;
            }
            {
                float mx = fmaxf(f0h, f1h), mn = fminf(f0h, f1h);
                float s = ss[ch1];
                float a = (s >= 0.f) ? mx : mn;
                if (((a - sm[ch1]) * s + sb[ch1]) >= 0.f) wloc |= 1ull << ch1;
            }
        }
        u64 other = __shfl_xor_sync(0xffffffffu, wloc, 1);
        u64 mk = *pmask;
        u64 wfin = ((wloc | other) & mk) | ((wloc & other) & ~mk);
        if (tid < 392 && h == 0) g_act1[b * 196 + p] = wfin;

    } else if (bid < 2048) {
        // fc1 weight sign -> s8 (+1 / -1); 6272 floats (2 rows) per block
        int base = (bid - 1024) * 6272;
        int off = tid * 16;
        if (off < 6272) {
            const float4* src = (const float4*)(wfc1 + base + off);
            u32 w[4];
            #pragma unroll
            for (int v4 = 0; v4 < 4; v4++) {
                float4 f = src[v4];
                u32 a0 = (f.x >= 0.f) ? 0x01u : 0xFFu;
                u32 a1 = (f.y >= 0.f) ? 0x01u : 0xFFu;
                u32 a2 = (f.z >= 0.f) ? 0x01u : 0xFFu;
                u32 a3 = (f.w >= 0.f) ? 0x01u : 0xFFu;
                w[v4] = a0 | (a1 << 8) | (a2 << 16) | (a3 << 24);
            }
            *(uint4*)(g_fc1s8 + base + off) = make_uint4(w[0], w[1], w[2], w[3]);
        }
    } else {
        for (int t = tid; t < 576; t += 416) {
            int o = t / 9, tap = t % 9;
            u64 word = 0ull;
            const float* base = w2 + o * 576 + tap;
            #pragma unroll 8
            for (int i = 0; i < 64; i++)
                if (base[i * 9] >= 0.f) word |= 1ull << i;
            g_w2[t] = word;
        }
    }
}

// ---------------- fc2 weight pack ----------------
__global__ void k_packfc2(const float* __restrict__ wfc2) {
    int t = blockIdx.x * blockDim.x + threadIdx.x;
    if (t >= 640) return;
    int o = t / 64, wi = t % 64;
    u32 word = 0u;
    const float* base = wfc2 + o * 2048 + wi * 32;
    #pragma unroll
    for (int b = 0; b < 32; b++)
        if (base[b] >= 0.f) word |= 1u << b;
    g_fc2b[t] = word;
}

// ---------------- stage 2: conv2 + bn2 + sign + maxpool2 -> s8 A matrix ----------------
__global__ void __launch_bounds__(416, 3)
k_conv2(const float* __restrict__ g2, const float* __restrict__ b2,
        const float* __restrict__ m2, const float* __restrict__ v2) {
    __shared__ u64 w2s[576];
    __shared__ u64 sAct[196];
    __shared__ u64 s2[49];
    __shared__ float sm[64], ss[64], sb[64];
    __shared__ u64 smask;
    int tid = threadIdx.x;
    int b = blockIdx.x;
    for (int i = tid; i < 576; i += 416) w2s[i] = g_w2[i];
    if (tid < 196) sAct[tid] = g_act1[b * 196 + tid];
    if (tid >= 196 && tid < 260) {
        int c = tid - 196;
        sm[c] = m2[c];
        ss[c] = g2[c] * (1.0f / sqrtf(v2[c] + 1e-5f));
        sb[c] = b2[c];
    }
    __syncthreads();
    if (tid == 0) {
        u64 mk = 0ull;
        for (int c = 0; c < 64; c++) if (ss[c] >= 0.f) mk |= 1ull << c;
        smask = mk;
    }
    __syncthreads();

    int t = tid < 392 ? tid : 391;
    int p   = t >> 3;
    int sub = t & 7;
    int cg  = sub >> 1;
    int h   = sub & 1;
    int py = p / 7, px = p % 7;

    u64 P[3][4];
    #pragma unroll
    for (int r = 0; r < 3; r++) {
        int yy = 2 * py - 1 + h + r; yy = yy < 0 ? 0 : (yy > 13 ? 13 : yy);
        #pragma unroll
        for (int c = 0; c < 4; c++) {
            int xx = 2 * px - 1 + c; xx = xx < 0 ? 0 : (xx > 13 ? 13 : xx);
            P[r][c] = sAct[yy * 14 + xx];
        }
    }

    u64 wloc = 0ull;
    int obase = cg * 16;
    #pragma unroll 4
    for (int oo = 0; oo < 16; oo++) {
        int o = obase + oo;
        const u64* wo = &w2s[o * 9];
        int d0 = 0, d1 = 0;
        #pragma unroll
        for (int dy = 0; dy < 3; dy++) {
            #pragma unroll
            for (int dx = 0; dx < 3; dx++) {
                u64 w = wo[dy * 3 + dx];
                d0 += __popcll(P[dy][dx]     ^ w);
                d1 += __popcll(P[dy][dx + 1] ^ w);
            }
        }
        int dmn = min(d0, d1), dmx = max(d0, d1);
        float s = ss[o];
        int dsel = (s >= 0.f) ? dmn : dmx;
        float sum = (float)(576 - 2 * dsel);
        if (((sum - sm[o]) * s + sb[o]) >= 0.f) wloc |= 1ull << o;
    }
    u64 other = __shfl_xor_sync(0xffffffffu, wloc, 1);
    u64 mk = smask;
    u64 v = ((wloc | other) & mk) | ((wloc & other) & ~mk);
    v |= __shfl_xor_sync(0xffffffffu, v, 2);
    v |= __shfl_xor_sync(0xffffffffu, v, 4);
    if (tid < 392 && sub == 0) s2[p] = v;
    __syncthreads();

    // emit s8 A row: A[b][ch*49+p] = +/-1
    if (tid < 392) {
        int e0 = tid * 8;
        u32 w0 = 0, w1 = 0;
        #pragma unroll
        for (int i = 0; i < 4; i++) {
            int e = e0 + i;
            int ch = e / 49, pp = e - ch * 49;
            w0 |= (((s2[pp] >> ch) & 1) ? 0x01u : 0xFFu) << (i * 8);
        }
        #pragma unroll
        for (int i = 0; i < 4; i++) {
            int e = e0 + 4 + i;
            int ch = e / 49, pp = e - ch * 49;
            w1 |= (((s2[pp] >> ch) & 1) ? 0x01u : 0xFFu) << (i * 8);
        }
        *(uint2*)(g_act2s8 + (size_t)b * 3136 + e0) = make_uint2(w0, w1);
    }
}

// ---------------- stage 3a: fc1 split-K mma GEMM -> s16 partials ----------------
// grid (16 ntiles, 8 mtiles, 2 splits); CTA 128x128, split 0: chunks 0..24, split 1: 25..48.
static constexpr int F1_STAGE = 20480;          // A[128][80] + B[128][80]
static constexpr int F1_SMEM  = 4 * F1_STAGE;   // 81920

extern __shared__ __align__(16) char f1sm[];
__global__ void __launch_bounds__(256, 2)
k_fc1mma() {
    int tid = threadIdx.x;
    int wid = tid >> 5, lid = tid & 31;
    int g = lid >> 2, tig = lid & 3;
    int wm = wid & 3, wn = wid >> 2;       // 4 warps M, 2 warps N
    int nt = blockIdx.x, mt = blockIdx.y;
    int split = blockIdx.z;
    int kbeg = split ? 25 : 0;
    int kcnt = split ? 24 : 25;

    const char* gA = g_act2s8 + (size_t)mt * 128 * 3136;
    const char* gB = g_fc1s8 + (size_t)nt * 128 * 3136;

    auto load_chunk = [&](int c) {
        char* As = f1sm + (c & 3) * F1_STAGE;
        char* Bs = As + 10240;
        const char* gAc = gA + (kbeg + c) * 64;
        const char* gBc = gB + (kbeg + c) * 64;
        #pragma unroll
        for (int i = 0; i < 4; i++) {
            int sg = tid * 4 + i;             // 0..1023
            int row = (sg >> 2) & 127;
            int q = sg & 3;
            bool isB = sg >= 512;
            const char* src = (isB ? gBc : gAc) + (size_t)row * 3136 + q * 16;
            char* dst = (isB ? Bs : As) + row * 80 + q * 16;
            cpa16(dst, src);
        }
        CPA_COMMIT();
    };

    int acc[2][8][4];
    #pragma unroll
    for (int mi = 0; mi < 2; mi++)
        #pragma unroll
        for (int ni = 0; ni < 8; ni++)
            #pragma unroll
            for (int q = 0; q < 4; q++) acc[mi][ni][q] = 0;

    load_chunk(0); load_chunk(1);
    for (int c = 0; c < kcnt; c++) {
        if (c + 2 < kcnt) { load_chunk(c + 2); CPA_WAIT2(); }
        else if (c + 1 < kcnt) { CPA_WAIT1(); }
        else { CPA_WAIT0(); }
        __syncthreads();

        const char* As = f1sm + (c & 3) * F1_STAGE;
        const char* Bs = As + 10240;
        #pragma unroll
        for (int ks = 0; ks < 2; ks++) {
            int kb = ks * 32 + tig * 4;
            u32 af[2][4];
            #pragma unroll
            for (int mi = 0; mi < 2; mi++) {
                int r = wm * 32 + mi * 16 + g;
                af[mi][0] = *(const u32*)(As + r * 80 + kb);
                af[mi][1] = *(const u32*)(As + (r + 8) * 80 + kb);
                af[mi][2] = *(const u32*)(As + r * 80 + kb + 16);
                af[mi][3] = *(const u32*)(As + (r + 8) * 80 + kb + 16);
            }
            u32 bf[8][2];
            #pragma unroll
            for (int ni = 0; ni < 8; ni++) {
                int r = wn * 64 + ni * 8 + g;
                bf[ni][0] = *(const u32*)(Bs + r * 80 + kb);
                bf[ni][1] = *(const u32*)(Bs + r * 80 + kb + 16);
            }
            #pragma unroll
            for (int mi = 0; mi < 2; mi++)
                #pragma unroll
                for (int ni = 0; ni < 8; ni++)
                    imma16832(acc[mi][ni], af[mi], bf[ni]);
        }
    }

    // store partial sums as s16 pairs: g_part[split][row][colpair]
    u32* gp = g_part[split];
    #pragma unroll
    for (int mi = 0; mi < 2; mi++) {
        int r0 = mt * 128 + wm * 32 + mi * 16 + g;
        #pragma unroll
        for (int ni = 0; ni < 8; ni++) {
            int cp = nt * 64 + wn * 32 + ni * 4 + tig;
            u32 v0 = ((u32)acc[mi][ni][0] & 0xFFFFu) | ((u32)acc[mi][ni][1] << 16);
            u32 v1 = ((u32)acc[mi][ni][2] & 0xFFFFu) | ((u32)acc[mi][ni][3] << 16);
            gp[(size_t)r0 * 1024 + cp]       = v0;
            gp[(size_t)(r0 + 8) * 1024 + cp] = v1;
        }
    }
}

// ---------------- stage 3b: combine partials + bn3 + sign -> g_act3 ----------------
// 256 blocks x 256 thr; block bid: word wi = bid>>2, m = (bid&3)*256 + tid.
__global__ void __launch_bounds__(256, 8)
k_fc1red(const float* __restrict__ g3, const float* __restrict__ b3,
         const float* __restrict__ m3, const float* __restrict__ v3) {
    __shared__ float sMean[32], sScale[32], sBias[32];
    int tid = threadIdx.x;
    int wi = blockIdx.x >> 2;
    int m = (blockIdx.x & 3) * 256 + tid;
    if (tid < 32) {
        int j = wi * 32 + tid;
        sMean[tid]  = m3[j];
        sScale[tid] = g3[j] * (1.0f / sqrtf(v3[j] + 1e-5f));
        sBias[tid]  = b3[j];
    }
    __syncthreads();

    const uint4* p0 = (const uint4*)(g_part[0] + (size_t)m * 1024 + wi * 16);
    const uint4* p1 = (const uint4*)(g_part[1] + (size_t)m * 1024 + wi * 16);
    u32 word = 0;
    #pragma unroll
    for (int q = 0; q < 4; q++) {
        uint4 a = p0[q], b = p1[q];
        u32 av[4] = {a.x, a.y, a.z, a.w};
        u32 bv[4] = {b.x, b.y, b.z, b.w};
        #pragma unroll
        for (int t = 0; t < 4; t++) {
            int s0 = (int)(short)(av[t] & 0xFFFFu) + (int)(short)(bv[t] & 0xFFFFu);
            int s1 = (int)(short)(av[t] >> 16)     + (int)(short)(bv[t] >> 16);
            int jj = q * 8 + t * 2;
            if (((float)s0 - sMean[jj]) * sScale[jj] + sBias[jj] >= 0.f)
                word |= 1u << jj;
            if (((float)s1 - sMean[jj + 1]) * sScale[jj + 1] + sBias[jj + 1] >= 0.f)
                word |= 1u << (jj + 1);
        }
    }
    g_act3[(size_t)m * 64 + wi] = word;
}

// ---------------- stage 4: fc2 + scale ----------------
__global__ void k_fc2(const float* __restrict__ scale, float* __restrict__ out) {
    int idx = blockIdx.x * blockDim.x + threadIdx.x;   // 40960
    if (idx >= 40960) return;
    int q = idx & 3;
    int rest = idx >> 2;
    int s = rest / 10, o = rest % 10;
    const uint4* a = (const uint4*)(g_act3 + s * 64) + q * 4;
    const uint4* w = (const uint4*)(g_fc2b + o * 64) + q * 4;
    int d = 0;
    #pragma unroll
    for (int k = 0; k < 4; k++) {
        uint4 av = a[k], wv = w[k];
        d += __popc(av.x ^ wv.x) + __popc(av.y ^ wv.y)
           + __popc(av.z ^ wv.z) + __popc(av.w ^ wv.w);
    }
    d += __shfl_xor_sync(0xffffffffu, d, 1);
    d += __shfl_xor_sync(0xffffffffu, d, 2);
    if (q == 0) out[s * 10 + o] = (float)(2048 - 2 * d) * scale[0];
}

// ---------------- launch ----------------
extern "C" void kernel_launch(void* const* d_in, const int* in_sizes, int n_in,
                              void* d_out, int out_size) {
    const float* x       = (const float*)d_in[0];
    const float* conv1_w = (const float*)d_in[1];
    const float* bn1_g   = (const float*)d_in[2];
    const float* bn1_b   = (const float*)d_in[3];
    const float* bn1_m   = (const float*)d_in[4];
    const float* bn1_v   = (const float*)d_in[5];
    const float* conv2_w = (const float*)d_in[6];
    const float* bn2_g   = (const float*)d_in[7];
    const float* bn2_b   = (const float*)d_in[8];
    const float* bn2_m   = (const float*)d_in[9];
    const float* bn2_v   = (const float*)d_in[10];
    const float* fc1_w   = (const float*)d_in[11];
    const float* bn3_g   = (const float*)d_in[12];
    const float* bn3_b   = (const float*)d_in[13];
    const float* bn3_m   = (const float*)d_in[14];
    const float* bn3_v   = (const float*)d_in[15];
    const float* fc2_w   = (const float*)d_in[16];
    const float* scale   = (const float*)d_in[17];
    float* out = (float*)d_out;

    // #0: conv1 + fc1 s8 weight convert + conv2 weight pack
    k_front<<<2049, 416>>>(x, conv1_w, bn1_g, bn1_b, bn1_m, bn1_v,
                           conv2_w, fc1_w);
    // #1: conv2 -> s8 A matrix (scalar, known-good)
    k_conv2<<<1024, 416>>>(bn2_g, bn2_b, bn2_m, bn2_v);
    // #2: tiny filler -> fc1mma lands at captured idx 3
    k_packfc2<<<3, 256>>>(fc2_w);
    // #3: fc1 split-K tensor-core GEMM (profiled)
    cudaFuncSetAttribute(k_fc1mma, cudaFuncAttributeMaxDynamicSharedMemorySize, F1_SMEM);
    {
        dim3 grid(16, 8, 2);
        k_fc1mma<<<grid, 256, F1_SMEM>>>();
    }
    // #4: combine + BN + sign
    k_fc1red<<<256, 256>>>(bn3_g, bn3_b, bn3_m, bn3_v);
    // #5
    k_fc2<<<160, 256>>>(scale, out);
}

// round 15
// speedup vs baseline: 1.0708x; 1.0708x over previous
#include <cuda_runtime.h>
#include <cstdint>

typedef unsigned long long u64;
typedef unsigned int u32;

// ---------------- scratch ----------------
__device__ u64 g_act1[1024 * 196];                        // [b][14x14], bit c = channel
__device__ __align__(16) char g_act2s8[1024 * 3136];      // A: s8 +/-1, k = ch*49+p
__device__ __align__(16) char g_fc1s8[2048 * 3136];       // B: s8 +/-1 fc1 weights
__device__ __align__(16) char g_w2s8[64 * 576];           // conv2 weights s8, k = tap*64+ch
__device__ u32 g_act3[1024 * 64];                         // [b][2048/32]
__device__ u32 g_fc2b[10 * 64];                           // fc2 w bits

// ---------------- f32x2 helpers ----------------
__device__ __forceinline__ u64 pk2(float lo, float hi) {
    u64 r; asm("mov.b64 %0, {%1,%2};" : "=l"(r) : "f"(lo), "f"(hi)); return r;
}
__device__ __forceinline__ void upk2(float& lo, float& hi, u64 v) {
    asm("mov.b64 {%0,%1}, %2;" : "=f"(lo), "=f"(hi) : "l"(v));
}
__device__ __forceinline__ u64 fma2(u64 a, u64 b, u64 c) {
    u64 d; asm("fma.rn.f32x2 %0, %1, %2, %3;" : "=l"(d) : "l"(a), "l"(b), "l"(c)); return d;
}

// ---------------- mma / cp.async helpers ----------------
__device__ __forceinline__ void imma16832(int* d, const u32* a, const u32* b) {
    asm volatile("mma.sync.aligned.m16n8k32.row.col.s32.s8.s8.s32 "
                 "{%0,%1,%2,%3}, {%4,%5,%6,%7}, {%8,%9}, {%0,%1,%2,%3};"
                 : "+r"(d[0]), "+r"(d[1]), "+r"(d[2]), "+r"(d[3])
                 : "r"(a[0]), "r"(a[1]), "r"(a[2]), "r"(a[3]),
                   "r"(b[0]), "r"(b[1]));
}
__device__ __forceinline__ void cpa16(void* dst, const void* src) {
    u32 d = (u32)__cvta_generic_to_shared(dst);
    asm volatile("cp.async.cg.shared.global [%0], [%1], 16;" :: "r"(d), "l"(src));
}
#define CPA_COMMIT() asm volatile("cp.async.commit_group;" ::: "memory")
#define CPA_WAIT2()  asm volatile("cp.async.wait_group 2;" ::: "memory")
#define CPA_WAIT1()  asm volatile("cp.async.wait_group 1;" ::: "memory")
#define CPA_WAIT0()  asm volatile("cp.async.wait_group 0;" ::: "memory")

// =====================================================================
// k_front: conv1 (0..1023), fc1 weight sign->s8 (1024..2047), conv2-w s8 (2048)
// =====================================================================
__global__ void __launch_bounds__(416, 3)
k_front(const float* __restrict__ x, const float* __restrict__ w1,
        const float* __restrict__ g1, const float* __restrict__ b1,
        const float* __restrict__ m1, const float* __restrict__ v1,
        const float* __restrict__ w2, const float* __restrict__ wfc1) {
    __shared__ __align__(16) char sraw[3328];
    int tid = threadIdx.x;
    int bid = blockIdx.x;

    if (bid < 1024) {
        float* ws = (float*)sraw;                       // [9][64]
        float* sm = (float*)(sraw + 2304);
        float* ss = (float*)(sraw + 2560);
        float* sb = (float*)(sraw + 2816);
        u64*  pmask = (u64*)(sraw + 3072);

        for (int i = tid; i < 576; i += 416) {
            int ch = i / 9, tap = i % 9;
            ws[tap * 64 + ch] = (w1[i] >= 0.f) ? 1.f : -1.f;
        }
        if (tid < 64) {
            sm[tid] = m1[tid];
            ss[tid] = g1[tid] * (1.0f / sqrtf(v1[tid] + 1e-5f));
            sb[tid] = b1[tid];
        }
        __syncthreads();
        if (tid == 0) {
            u64 mk = 0ull;
            for (int c = 0; c < 64; c++) if (ss[c] >= 0.f) mk |= 1ull << c;
            *pmask = mk;
        }
        __syncthreads();

        int b = bid;
        int t = tid < 392 ? tid : 391;
        int p = t >> 1, h = t & 1;
        int py = p / 14, px = p % 14;
        const float* xb = x + b * 784;

        u64 P[3][4];
        #pragma unroll
        for (int r = 0; r < 3; r++) {
            int yy = 2 * py - 1 + h + r; yy = yy < 0 ? 0 : (yy > 27 ? 27 : yy);
            #pragma unroll
            for (int c = 0; c < 4; c++) {
                int xx = 2 * px - 1 + c; xx = xx < 0 ? 0 : (xx > 27 ? 27 : xx);
                float v = xb[yy * 28 + xx];
                P[r][c] = pk2(v, v);
            }
        }

        const u64* wrow = (const u64*)ws;
        u64 wloc = 0ull;
        #pragma unroll 2
        for (int cp = 0; cp < 32; cp++) {
            u64 wt[9];
            #pragma unroll
            for (int k = 0; k < 9; k++) wt[k] = wrow[k * 32 + cp];
            u64 a0 = 0, a1 = 0;
            #pragma unroll
            for (int dy = 0; dy < 3; dy++) {
                #pragma unroll
                for (int dx = 0; dx < 3; dx++) {
                    int k = dy * 3 + dx;
                    a0 = fma2(wt[k], P[dy][dx],     a0);
                    a1 = fma2(wt[k], P[dy][dx + 1], a1);
                }
            }
            float f0l, f0h, f1l, f1h;
            upk2(f0l, f0h, a0); upk2(f1l, f1h, a1);
            int ch0 = 2 * cp, ch1 = ch0 + 1;
            {
                float mx = fmaxf(f0l, f1l), mn = fminf(f0l, f1l);
                float s = ss[ch0];
                float a = (s >= 0.f) ? mx : mn;
                if (((a - sm[ch0]) * s + sb[ch0]) >= 0.f) wloc |= 1ull << ch0;
            }
            {
                float mx = fmaxf(f0h, f1h), mn = fminf(f0h, f1h);
                float s = ss[ch1];
                float a = (s >= 0.f) ? mx : mn;
                if (((a - sm[ch1]) * s + sb[ch1]) >= 0.f) wloc |= 1ull << ch1;
            }
        }
        u64 other = __shfl_xor_sync(0xffffffffu, wloc, 1);
        u64 mk = *pmask;
        u64 wfin = ((wloc | other) & mk) | ((wloc & other) & ~mk);
        if (tid < 392 && h == 0) g_act1[b * 196 + p] = wfin;

    } else if (bid < 2048) {
        // fc1 weight sign -> s8 (+1 / -1); 6272 floats (2 rows) per block
        int base = (bid - 1024) * 6272;
        int off = tid * 16;
        if (off < 6272) {
            const float4* src = (const float4*)(wfc1 + base + off);
            u32 w[4];
            #pragma unroll
            for (int v4 = 0; v4 < 4; v4++) {
                float4 f = src[v4];
                u32 a0 = (f.x >= 0.f) ? 0x01u : 0xFFu;
                u32 a1 = (f.y >= 0.f) ? 0x01u : 0xFFu;
                u32 a2 = (f.z >= 0.f) ? 0x01u : 0xFFu;
                u32 a3 = (f.w >= 0.f) ? 0x01u : 0xFFu;
                w[v4] = a0 | (a1 << 8) | (a2 << 16) | (a3 << 24);
            }
            *(uint4*)(g_fc1s8 + base + off) = make_uint4(w[0], w[1], w[2], w[3]);
        }
    } else {
        // conv2 weights -> s8, k = tap*64 + ch
        for (int t = tid; t < 576; t += 416) {
            int o = t / 9, tap = t % 9;
            const float* base = w2 + o * 576 + tap;
            u32* dst = (u32*)(g_w2s8 + o * 576 + tap * 64);
            #pragma unroll 4
            for (int q = 0; q < 16; q++) {
                u32 wv = 0;
                #pragma unroll
                for (int j = 0; j < 4; j++)
                    wv |= ((base[(q * 4 + j) * 9] >= 0.f) ? 0x01u : 0xFFu) << (j * 8);
                dst[q] = wv;
            }
        }
    }
}

// ---------------- fc2 weight pack, split (launch-slot fillers) ----------------
__global__ void k_packfc2a(const float* __restrict__ wfc2) {
    int t = blockIdx.x * blockDim.x + threadIdx.x;
    if (t >= 320) return;
    int o = t / 64, wi = t % 64;
    u32 word = 0u;
    const float* base = wfc2 + o * 2048 + wi * 32;
    #pragma unroll
    for (int b = 0; b < 32; b++)
        if (base[b] >= 0.f) word |= 1u << b;
    g_fc2b[t] = word;
}
__global__ void k_packfc2b(const float* __restrict__ wfc2) {
    int t = blockIdx.x * blockDim.x + threadIdx.x + 320;
    if (t >= 640) return;
    int o = t / 64, wi = t % 64;
    u32 word = 0u;
    const float* base = wfc2 + o * 2048 + wi * 32;
    #pragma unroll
    for (int b = 0; b < 32; b++)
        if (base[b] >= 0.f) word |= 1u << b;
    g_fc2b[t] = word;
}

// =====================================================================
// stage 2: conv2 via mma.sync. 1 CTA = 1 sample, 256 threads.
// K = tap*64+ch, 9 taps x 2 K-steps of m16n8k32.
// R11 bug fixed: pool/emit epilogues now LOOP over 392 work items.
// =====================================================================
static constexpr int C2_EXP  = 0;       // 208*72 = 14976
static constexpr int C2_B    = 14976;   // 64*592 = 37888
static constexpr int C2_ROW  = 52864;   // 9*208  = 1872
static constexpr int C2_LUT  = 54736;   // 64
static constexpr int C2_POOL = 54800;   // 49*8
static constexpr int C2_BN   = 55200;   // 3*64*4
static constexpr int C2_SMEM = 55968;

extern __shared__ __align__(16) char dsm[];
__global__ void __launch_bounds__(256, 2)
k_conv2mma(const float* __restrict__ g2, const float* __restrict__ b2,
           const float* __restrict__ m2, const float* __restrict__ v2) {
    int tid = threadIdx.x;
    int wid = tid >> 5, lid = tid & 31;
    int g = lid >> 2, tig = lid & 3;
    int wm = wid & 3, wn = wid >> 2;
    int b = blockIdx.x;

    char* sExp = dsm + C2_EXP;                 // [208][72] s8 (196 real rows)
    char* sB   = dsm + C2_B;                   // [64][592] s8
    unsigned char* sRowA = (unsigned char*)(dsm + C2_ROW);
    u32* lut = (u32*)(dsm + C2_LUT);
    float* sMean  = (float*)(dsm + C2_BN);
    float* sScale = (float*)(dsm + C2_BN + 256);
    float* sBias  = (float*)(dsm + C2_BN + 512);

    // B tile: 64 rows x 576 bytes = 2304 cpa16
    #pragma unroll
    for (int i = 0; i < 9; i++) {
        int sg = tid * 9 + i;
        int row = sg / 36, q = sg % 36;
        cpa16(sB + row * 592 + q * 16, g_w2s8 + row * 576 + q * 16);
    }
    CPA_COMMIT();

    if (tid < 16) {
        lut[tid] = ((tid & 1) ? 0x01u : 0xFFu)
                 | (((tid >> 1) & 1) ? 0x0100u : 0xFF00u)
                 | (((tid >> 2) & 1) ? 0x010000u : 0xFF0000u)
                 | (((tid >> 3) & 1) ? 0x01000000u : 0xFF000000u);
    }
    if (tid >= 64 && tid < 128) {
        int c = tid - 64;
        sMean[c]  = m2[c];
        sScale[c] = g2[c] * (1.0f / sqrtf(v2[c] + 1e-5f));
        sBias[c]  = b2[c];
    }
    __syncthreads();   // lut visible

    // expand act1 bits -> s8 rows
    if (tid < 196) {
        u64 w = g_act1[b * 196 + tid];
        u32* dst = (u32*)(sExp + tid * 72);
        #pragma unroll
        for (int j = 0; j < 16; j++)
            dst[j] = lut[(w >> (4 * j)) & 15];
    }
    // im2col row map (replicate clamp); rows >=196 are padding (clamped, unused)
    for (int i = tid; i < 9 * 208; i += 256) {
        int tap = i / 208, p = i - tap * 208;
        int pos = p < 196 ? p : 195;
        int y = pos / 14, x = pos % 14;
        int dy = tap / 3 - 1, dx = tap % 3 - 1;
        int yy = min(max(y + dy, 0), 13);
        int xx = min(max(x + dx, 0), 13);
        sRowA[i] = (unsigned char)(yy * 14 + xx);
    }
    CPA_WAIT0();
    __syncthreads();

    int acc[4][4][4];
    #pragma unroll
    for (int a = 0; a < 4; a++)
        #pragma unroll
        for (int n = 0; n < 4; n++)
            #pragma unroll
            for (int q = 0; q < 4; q++) acc[a][n][q] = 0;

    int nm = (wm == 0) ? 4 : 3;    // m-tiles: wm, wm+4, wm+8 (+12 for wm==0)

    #pragma unroll
    for (int tap = 0; tap < 9; tap++) {
        int r0[4], r8[4];
        #pragma unroll
        for (int mi = 0; mi < 4; mi++) {
            if (mi < nm) {
                int r = (wm + 4 * mi) * 16;
                r0[mi] = sRowA[tap * 208 + r + g];
                r8[mi] = sRowA[tap * 208 + r + 8 + g];
            }
        }
        #pragma unroll
        for (int ks = 0; ks < 2; ks++) {
            int kb = ks * 32 + tig * 4;
            u32 af[4][4];
            #pragma unroll
            for (int mi = 0; mi < 4; mi++) {
                if (mi < nm) {
                    af[mi][0] = *(const u32*)(sExp + r0[mi] * 72 + kb);
                    af[mi][1] = *(const u32*)(sExp + r8[mi] * 72 + kb);
                    af[mi][2] = *(const u32*)(sExp + r0[mi] * 72 + kb + 16);
                    af[mi][3] = *(const u32*)(sExp + r8[mi] * 72 + kb + 16);
                }
            }
            u32 bf[4][2];
            #pragma unroll
            for (int ni = 0; ni < 4; ni++) {
                int rb = wn * 32 + ni * 8 + g;
                bf[ni][0] = *(const u32*)(sB + rb * 592 + tap * 64 + kb);
                bf[ni][1] = *(const u32*)(sB + rb * 592 + tap * 64 + kb + 16);
            }
            #pragma unroll
            for (int mi = 0; mi < 4; mi++)
                if (mi < nm)
                    #pragma unroll
                    for (int ni = 0; ni < 4; ni++)
                        imma16832(acc[mi][ni], af[mi], bf[ni]);
        }
    }
    __syncthreads();   // all mma reads done before smem overlay

    // stage sums [196][64] s32 (overlay over sExp+sB region)
    int* sums = (int*)dsm;
    #pragma unroll
    for (int mi = 0; mi < 4; mi++) {
        if (mi < nm) {
            #pragma unroll
            for (int ni = 0; ni < 4; ni++) {
                int mrow0 = (wm + 4 * mi) * 16 + g;
                int mrow1 = mrow0 + 8;
                int c0 = wn * 32 + ni * 8 + tig * 2;
                if (mrow0 < 196) *(int2*)(sums + mrow0 * 64 + c0) = make_int2(acc[mi][ni][0], acc[mi][ni][1]);
                if (mrow1 < 196) *(int2*)(sums + mrow1 * 64 + c0) = make_int2(acc[mi][ni][2], acc[mi][ni][3]);
            }
        }
    }
    __syncthreads();

    // maxpool 2x2 (monotone select) + BN + sign -> byte mask  [FIXED: loop 392]
    u64* sPool = (u64*)(dsm + C2_POOL);
    for (int t = tid; t < 392; t += 256) {
        int p = t >> 3, cs = t & 7;
        int py = p / 7, px = p % 7;
        int b00 = ((py * 2) * 14 + px * 2) * 64;
        int b01 = b00 + 64, b10 = b00 + 14 * 64, b11 = b10 + 64;
        u32 msk = 0;
        #pragma unroll
        for (int j = 0; j < 8; j++) {
            int c = cs * 8 + j;
            int s00 = sums[b00 + c], s01 = sums[b01 + c];
            int s10 = sums[b10 + c], s11 = sums[b11 + c];
            int mx = max(max(s00, s01), max(s10, s11));
            int mn = min(min(s00, s01), min(s10, s11));
            float s = sScale[c];
            int sel = (s >= 0.f) ? mx : mn;
            if (((float)sel - sMean[c]) * s + sBias[c] >= 0.f) msk |= 1u << j;
        }
        ((unsigned char*)sPool)[p * 8 + cs] = (unsigned char)msk;
    }
    __syncthreads();

    // emit s8 A row for fc1: A[b][ch*49+p]   [FIXED: loop 392]
    for (int t = tid; t < 392; t += 256) {
        int e0 = t * 8;
        u32 w0 = 0, w1 = 0;
        #pragma unroll
        for (int i = 0; i < 4; i++) {
            int e = e0 + i;
            int ch = e / 49, pp = e - ch * 49;
            w0 |= (((sPool[pp] >> ch) & 1) ? 0x01u : 0xFFu) << (i * 8);
        }
        #pragma unroll
        for (int i = 0; i < 4; i++) {
            int e = e0 + 4 + i;
            int ch = e / 49, pp = e - ch * 49;
            w1 |= (((sPool[pp] >> ch) & 1) ? 0x01u : 0xFFu) << (i * 8);
        }
        *(uint2*)(g_act2s8 + (size_t)b * 3136 + e0) = make_uint2(w0, w1);
    }
}

// ---------------- stage 3: fc1 = s8 mma GEMM (R13: 4-stage pipeline, 128 CTAs) ----------------
static constexpr int F1_STAGE = 20480;          // A[128][80] + B[128][80]
static constexpr int F1_BN    = 4 * F1_STAGE;   // 81920
static constexpr int F1_SMEM  = F1_BN + 3 * 128 * 4;   // 83456

extern __shared__ __align__(16) char f1sm[];
__global__ void __launch_bounds__(256, 1)
k_fc1mma(const float* __restrict__ g3, const float* __restrict__ b3,
         const float* __restrict__ m3, const float* __restrict__ v3) {
    int tid = threadIdx.x;
    int wid = tid >> 5, lid = tid & 31;
    int g = lid >> 2, tig = lid & 3;
    int wm = wid & 3, wn = wid >> 2;       // 4 warps M, 2 warps N
    int nt = blockIdx.x, mt = blockIdx.y;

    float* sMean  = (float*)(f1sm + F1_BN);
    float* sScale = (float*)(f1sm + F1_BN + 512);
    float* sBias  = (float*)(f1sm + F1_BN + 1024);

    const char* gA = g_act2s8 + (size_t)mt * 128 * 3136;
    const char* gB = g_fc1s8 + (size_t)nt * 128 * 3136;

    if (tid < 128) {
        int j = nt * 128 + tid;
        sMean[tid]  = m3[j];
        sScale[tid] = g3[j] * (1.0f / sqrtf(v3[j] + 1e-5f));
        sBias[tid]  = b3[j];
    }

    auto load_chunk = [&](int c) {
        char* As = f1sm + (c & 3) * F1_STAGE;
        char* Bs = As + 10240;
        const char* gAc = gA + c * 64;
        const char* gBc = gB + c * 64;
        #pragma unroll
        for (int i = 0; i < 4; i++) {
            int sg = tid * 4 + i;             // 0..1023
            int row = (sg >> 2) & 127;
            int q = sg & 3;
            bool isB = sg >= 512;
            const char* src = (isB ? gBc : gAc) + (size_t)row * 3136 + q * 16;
            char* dst = (isB ? Bs : As) + row * 80 + q * 16;
            cpa16(dst, src);
        }
        CPA_COMMIT();
    };

    int acc[2][8][4];
    #pragma unroll
    for (int mi = 0; mi < 2; mi++)
        #pragma unroll
        for (int ni = 0; ni < 8; ni++)
            #pragma unroll
            for (int q = 0; q < 4; q++) acc[mi][ni][q] = 0;

    load_chunk(0); load_chunk(1);
    for (int c = 0; c < 49; c++) {
        if (c + 2 < 49) { load_chunk(c + 2); CPA_WAIT2(); }
        else if (c + 1 < 49) { CPA_WAIT1(); }
        else { CPA_WAIT0(); }
        __syncthreads();

        const char* As = f1sm + (c & 3) * F1_STAGE;
        const char* Bs = As + 10240;
        #pragma unroll
        for (int ks = 0; ks < 2; ks++) {
            int kb = ks * 32 + tig * 4;
            u32 af[2][4];
            #pragma unroll
            for (int mi = 0; mi < 2; mi++) {
                int r = wm * 32 + mi * 16 + g;
                af[mi][0] = *(const u32*)(As + r * 80 + kb);
                af[mi][1] = *(const u32*)(As + (r + 8) * 80 + kb);
                af[mi][2] = *(const u32*)(As + r * 80 + kb + 16);
                af[mi][3] = *(const u32*)(As + (r + 8) * 80 + kb + 16);
            }
            u32 bf[8][2];
            #pragma unroll
            for (int ni = 0; ni < 8; ni++) {
                int r = wn * 64 + ni * 8 + g;
                bf[ni][0] = *(const u32*)(Bs + r * 80 + kb);
                bf[ni][1] = *(const u32*)(Bs + r * 80 + kb + 16);
            }
            #pragma unroll
            for (int mi = 0; mi < 2; mi++)
                #pragma unroll
                for (int ni = 0; ni < 8; ni++)
                    imma16832(acc[mi][ni], af[mi], bf[ni]);
        }
    }
    __syncthreads();   // all reads done before smem reuse

    // epilogue: BN + sign -> byte stage (per-warp [32][64]) -> packed u32 words
    char* bw = f1sm + wid * 2048;
    #pragma unroll
    for (int mi = 0; mi < 2; mi++) {
        #pragma unroll
        for (int ni = 0; ni < 8; ni++) {
            int cc0 = ni * 8 + tig * 2;
            int jj0 = wn * 64 + cc0;
            float m0 = sMean[jj0], s0 = sScale[jj0], bb0 = sBias[jj0];
            float m1 = sMean[jj0 + 1], s1 = sScale[jj0 + 1], bb1 = sBias[jj0 + 1];
            int r0 = mi * 16 + g, r1 = r0 + 8;
            bw[r0 * 64 + cc0]     = (((float)acc[mi][ni][0] - m0) * s0 + bb0 >= 0.f);
            bw[r0 * 64 + cc0 + 1] = (((float)acc[mi][ni][1] - m1) * s1 + bb1 >= 0.f);
            bw[r1 * 64 + cc0]     = (((float)acc[mi][ni][2] - m0) * s0 + bb0 >= 0.f);
            bw[r1 * 64 + cc0 + 1] = (((float)acc[mi][ni][3] - m1) * s1 + bb1 >= 0.f);
        }
    }
    __syncwarp();
    {
        int r = lid;
        const u32* bu = (const u32*)(bw + r * 64);
        u32 w0 = 0, w1 = 0;
        #pragma unroll
        for (int q = 0; q < 8; q++) {
            u32 v = bu[q];
            w0 |= ((v & 1u) << (q * 4)) | (((v >> 8) & 1u) << (q * 4 + 1))
                | (((v >> 16) & 1u) << (q * 4 + 2)) | (((v >> 24) & 1u) << (q * 4 + 3));
        }
        #pragma unroll
        for (int q = 0; q < 8; q++) {
            u32 v = bu[8 + q];
            w1 |= ((v & 1u) << (q * 4)) | (((v >> 8) & 1u) << (q * 4 + 1))
                | (((v >> 16) & 1u) << (q * 4 + 2)) | (((v >> 24) & 1u) << (q * 4 + 3));
        }
        int m = mt * 128 + wm * 32 + r;
        g_act3[(size_t)m * 64 + nt * 4 + wn * 2]     = w0;
        g_act3[(size_t)m * 64 + nt * 4 + wn * 2 + 1] = w1;
    }
}

// ---------------- stage 4: fc2 + scale ----------------
__global__ void k_fc2(const float* __restrict__ scale, float* __restrict__ out) {
    int idx = blockIdx.x * blockDim.x + threadIdx.x;   // 40960
    if (idx >= 40960) return;
    int q = idx & 3;
    int rest = idx >> 2;
    int s = rest / 10, o = rest % 10;
    const uint4* a = (const uint4*)(g_act3 + s * 64) + q * 4;
    const uint4* w = (const uint4*)(g_fc2b + o * 64) + q * 4;
    int d = 0;
    #pragma unroll
    for (int k = 0; k < 4; k++) {
        uint4 av = a[k], wv = w[k];
        d += __popc(av.x ^ wv.x) + __popc(av.y ^ wv.y)
           + __popc(av.z ^ wv.z) + __popc(av.w ^ wv.w);
    }
    d += __shfl_xor_sync(0xffffffffu, d, 1);
    d += __shfl_xor_sync(0xffffffffu, d, 2);
    if (q == 0) out[s * 10 + o] = (float)(2048 - 2 * d) * scale[0];
}

// ---------------- launch ----------------
extern "C" void kernel_launch(void* const* d_in, const int* in_sizes, int n_in,
                              void* d_out, int out_size) {
    const float* x       = (const float*)d_in[0];
    const float* conv1_w = (const float*)d_in[1];
    const float* bn1_g   = (const float*)d_in[2];
    const float* bn1_b   = (const float*)d_in[3];
    const float* bn1_m   = (const float*)d_in[4];
    const float* bn1_v   = (const float*)d_in[5];
    const float* conv2_w = (const float*)d_in[6];
    const float* bn2_g   = (const float*)d_in[7];
    const float* bn2_b   = (const float*)d_in[8];
    const float* bn2_m   = (const float*)d_in[9];
    const float* bn2_v   = (const float*)d_in[10];
    const float* fc1_w   = (const float*)d_in[11];
    const float* bn3_g   = (const float*)d_in[12];
    const float* bn3_b   = (const float*)d_in[13];
    const float* bn3_m   = (const float*)d_in[14];
    const float* bn3_v   = (const float*)d_in[15];
    const float* fc2_w   = (const float*)d_in[16];
    const float* scale   = (const float*)d_in[17];
    float* out = (float*)d_out;

    // #0: conv1 + fc1 s8 weight convert + conv2 s8 weight expand
    k_front<<<2049, 416>>>(x, conv1_w, bn1_g, bn1_b, bn1_m, bn1_v,
                           conv2_w, fc1_w);
    // #1,#2: tiny fillers -> conv2mma lands at captured idx 3
    k_packfc2a<<<2, 192>>>(fc2_w);
    k_packfc2b<<<2, 192>>>(fc2_w);
    // #3: conv2 tensor-core (profiled)
    cudaFuncSetAttribute(k_conv2mma, cudaFuncAttributeMaxDynamicSharedMemorySize, C2_SMEM);
    k_conv2mma<<<1024, 256, C2_SMEM>>>(bn2_g, bn2_b, bn2_m, bn2_v);
    // #4: fc1 tensor-core GEMM (R13 config)
    cudaFuncSetAttribute(k_fc1mma, cudaFuncAttributeMaxDynamicSharedMemorySize, F1_SMEM);
    {
        dim3 grid(16, 8);
        k_fc1mma<<<grid, 256, F1_SMEM>>>(bn3_g, bn3_b, bn3_m, bn3_v);
    }
    // #5
    k_fc2<<<160, 256>>>(scale, out);
}

// round 17
// speedup vs baseline: 1.0843x; 1.0127x over previous
#include <cuda_runtime.h>
#include <cstdint>

typedef unsigned long long u64;
typedef unsigned int u32;

// ---------------- scratch ----------------
__device__ u64 g_act1[1024 * 196];                        // [b][14x14], bit c = channel
__device__ __align__(16) char g_act2s8[1024 * 3136];      // A: s8 +/-1, k = ch*49+p
__device__ __align__(16) char g_fc1s8[2048 * 3136];       // B: s8 +/-1 fc1 weights
__device__ __align__(16) char g_w2s8[64 * 576];           // conv2 weights s8, k = tap*64+ch
__device__ u32 g_act3[1024 * 64];                         // [b][2048/32]
__device__ u32 g_fc2b[10 * 64];                           // fc2 w bits

// ---------------- f32x2 helpers ----------------
__device__ __forceinline__ u64 pk2(float lo, float hi) {
    u64 r; asm("mov.b64 %0, {%1,%2};" : "=l"(r) : "f"(lo), "f"(hi)); return r;
}
__device__ __forceinline__ void upk2(float& lo, float& hi, u64 v) {
    asm("mov.b64 {%0,%1}, %2;" : "=f"(lo), "=f"(hi) : "l"(v));
}
__device__ __forceinline__ u64 fma2(u64 a, u64 b, u64 c) {
    u64 d; asm("fma.rn.f32x2 %0, %1, %2, %3;" : "=l"(d) : "l"(a), "l"(b), "l"(c)); return d;
}

// ---------------- mma / cp.async / ldmatrix helpers ----------------
__device__ __forceinline__ void imma16832(int* d, const u32* a, const u32* b) {
    asm volatile("mma.sync.aligned.m16n8k32.row.col.s32.s8.s8.s32 "
                 "{%0,%1,%2,%3}, {%4,%5,%6,%7}, {%8,%9}, {%0,%1,%2,%3};"
                 : "+r"(d[0]), "+r"(d[1]), "+r"(d[2]), "+r"(d[3])
                 : "r"(a[0]), "r"(a[1]), "r"(a[2]), "r"(a[3]),
                   "r"(b[0]), "r"(b[1]));
}
__device__ __forceinline__ void ldm_x4(u32* r, u32 addr) {
    asm volatile("ldmatrix.sync.aligned.m8n8.x4.shared.b16 {%0,%1,%2,%3}, [%4];"
                 : "=r"(r[0]), "=r"(r[1]), "=r"(r[2]), "=r"(r[3]) : "r"(addr));
}
__device__ __forceinline__ void ldm_x2(u32* r, u32 addr) {
    asm volatile("ldmatrix.sync.aligned.m8n8.x2.shared.b16 {%0,%1}, [%2];"
                 : "=r"(r[0]), "=r"(r[1]) : "r"(addr));
}
__device__ __forceinline__ void cpa16(void* dst, const void* src) {
    u32 d = (u32)__cvta_generic_to_shared(dst);
    asm volatile("cp.async.cg.shared.global [%0], [%1], 16;" :: "r"(d), "l"(src));
}
#define CPA_COMMIT() asm volatile("cp.async.commit_group;" ::: "memory")
#define CPA_WAIT2()  asm volatile("cp.async.wait_group 2;" ::: "memory")
#define CPA_WAIT1()  asm volatile("cp.async.wait_group 1;" ::: "memory")
#define CPA_WAIT0()  asm volatile("cp.async.wait_group 0;" ::: "memory")

// =====================================================================
// k_front: conv1 (0..1023), fc1 weight sign->s8 (1024..2047), conv2-w s8 (2048)
// =====================================================================
__global__ void __launch_bounds__(416, 3)
k_front(const float* __restrict__ x, const float* __restrict__ w1,
        const float* __restrict__ g1, const float* __restrict__ b1,
        const float* __restrict__ m1, const float* __restrict__ v1,
        const float* __restrict__ w2, const float* __restrict__ wfc1) {
    __shared__ __align__(16) char sraw[3328];
    int tid = threadIdx.x;
    int bid = blockIdx.x;

    if (bid < 1024) {
        float* ws = (float*)sraw;                       // [9][64]
        float* sm = (float*)(sraw + 2304);
        float* ss = (float*)(sraw + 2560);
        float* sb = (float*)(sraw + 2816);
        u64*  pmask = (u64*)(sraw + 3072);

        for (int i = tid; i < 576; i += 416) {
            int ch = i / 9, tap = i % 9;
            ws[tap * 64 + ch] = (w1[i] >= 0.f) ? 1.f : -1.f;
        }
        if (tid < 64) {
            sm[tid] = m1[tid];
            ss[tid] = g1[tid] * (1.0f / sqrtf(v1[tid] + 1e-5f));
            sb[tid] = b1[tid];
        }
        __syncthreads();
        if (tid == 0) {
            u64 mk = 0ull;
            for (int c = 0; c < 64; c++) if (ss[c] >= 0.f) mk |= 1ull << c;
            *pmask = mk;
        }
        __syncthreads();

        int b = bid;
        int t = tid < 392 ? tid : 391;
        int p = t >> 1, h = t & 1;
        int py = p / 14, px = p % 14;
        const float* xb = x + b * 784;

        u64 P[3][4];
        #pragma unroll
        for (int r = 0; r < 3; r++) {
            int yy = 2 * py - 1 + h + r; yy = yy < 0 ? 0 : (yy > 27 ? 27 : yy);
            #pragma unroll
            for (int c = 0; c < 4; c++) {
                int xx = 2 * px - 1 + c; xx = xx < 0 ? 0 : (xx > 27 ? 27 : xx);
                float v = xb[yy * 28 + xx];
                P[r][c] = pk2(v, v);
            }
        }

        const u64* wrow = (const u64*)ws;
        u64 wloc = 0ull;
        #pragma unroll 2
        for (int cp = 0; cp < 32; cp++) {
            u64 wt[9];
            #pragma unroll
            for (int k = 0; k < 9; k++) wt[k] = wrow[k * 32 + cp];
            u64 a0 = 0, a1 = 0;
            #pragma unroll
            for (int dy = 0; dy < 3; dy++) {
                #pragma unroll
                for (int dx = 0; dx < 3; dx++) {
                    int k = dy * 3 + dx;
                    a0 = fma2(wt[k], P[dy][dx],     a0);
                    a1 = fma2(wt[k], P[dy][dx + 1], a1);
                }
            }
            float f0l, f0h, f1l, f1h;
            upk2(f0l, f0h, a0); upk2(f1l, f1h, a1);
            int ch0 = 2 * cp, ch1 = ch0 + 1;
            {
                float mx = fmaxf(f0l, f1l), mn = fminf(f0l, f1l);
                float s = ss[ch0];
                float a = (s >= 0.f) ? mx : mn;
                if (((a - sm[ch0]) * s + sb[ch0]) >= 0.f) wloc |= 1ull << ch0;
            }
            {
                float mx = fmaxf(f0h, f1h), mn = fminf(f0h, f1h);
                float s = ss[ch1];
                float a = (s >= 0.f) ? mx : mn;
                if (((a - sm[ch1]) * s + sb[ch1]) >= 0.f) wloc |= 1ull << ch1;
            }
        }
        u64 other = __shfl_xor_sync(0xffffffffu, wloc, 1);
        u64 mk = *pmask;
        u64 wfin = ((wloc | other) & mk) | ((wloc & other) & ~mk);
        if (tid < 392 && h == 0) g_act1[b * 196 + p] = wfin;

    } else if (bid < 2048) {
        // fc1 weight sign -> s8 (+1 / -1); 6272 floats (2 rows) per block
        int base = (bid - 1024) * 6272;
        int off = tid * 16;
        if (off < 6272) {
            const float4* src = (const float4*)(wfc1 + base + off);
            u32 w[4];
            #pragma unroll
            for (int v4 = 0; v4 < 4; v4++) {
                float4 f = src[v4];
                u32 a0 = (f.x >= 0.f) ? 0x01u : 0xFFu;
                u32 a1 = (f.y >= 0.f) ? 0x01u : 0xFFu;
                u32 a2 = (f.z >= 0.f) ? 0x01u : 0xFFu;
                u32 a3 = (f.w >= 0.f) ? 0x01u : 0xFFu;
                w[v4] = a0 | (a1 << 8) | (a2 << 16) | (a3 << 24);
            }
            *(uint4*)(g_fc1s8 + base + off) = make_uint4(w[0], w[1], w[2], w[3]);
        }
    } else {
        // conv2 weights -> s8, k = tap*64 + ch
        for (int t = tid; t < 576; t += 416) {
            int o = t / 9, tap = t % 9;
            const float* base = w2 + o * 576 + tap;
            u32* dst = (u32*)(g_w2s8 + o * 576 + tap * 64);
            #pragma unroll 4
            for (int q = 0; q < 16; q++) {
                u32 wv = 0;
                #pragma unroll
                for (int j = 0; j < 4; j++)
                    wv |= ((base[(q * 4 + j) * 9] >= 0.f) ? 0x01u : 0xFFu) << (j * 8);
                dst[q] = wv;
            }
        }
    }
}

// ---------------- fc2 weight pack, split (launch-slot fillers) ----------------
__global__ void k_packfc2a(const float* __restrict__ wfc2) {
    int t = blockIdx.x * blockDim.x + threadIdx.x;
    if (t >= 320) return;
    int o = t / 64, wi = t % 64;
    u32 word = 0u;
    const float* base = wfc2 + o * 2048 + wi * 32;
    #pragma unroll
    for (int b = 0; b < 32; b++)
        if (base[b] >= 0.f) word |= 1u << b;
    g_fc2b[t] = word;
}
__global__ void k_packfc2b(const float* __restrict__ wfc2) {
    int t = blockIdx.x * blockDim.x + threadIdx.x + 320;
    if (t >= 640) return;
    int o = t / 64, wi = t % 64;
    u32 word = 0u;
    const float* base = wfc2 + o * 2048 + wi * 32;
    #pragma unroll
    for (int b = 0; b < 32; b++)
        if (base[b] >= 0.f) word |= 1u << b;
    g_fc2b[t] = word;
}

// =====================================================================
// stage 2: conv2 via mma.sync + ldmatrix fragment loads.
// 1 CTA = 1 sample, 256 threads. K = tap*64+ch, 9 taps x 2 K-steps.
// Expansion row stride 80 (16-byte aligned rows for ldmatrix).
// =====================================================================
static constexpr int C2_EXP  = 0;       // 208*80 = 16640
static constexpr int C2_B    = 16640;   // 64*592 = 37888 -> 54528
static constexpr int C2_ROW  = 54528;   // 9*208  = 1872  -> 56400
static constexpr int C2_LUT  = 56400;   // 64            -> 56464
static constexpr int C2_POOL = 56464;   // 49*8 = 392 (+pad) -> 56864
static constexpr int C2_BN   = 56864;   // 3*64*4 = 768  -> 57632
static constexpr int C2_SMEM = 57664;

extern __shared__ __align__(16) char dsm[];
__global__ void __launch_bounds__(256, 2)
k_conv2mma(const float* __restrict__ g2, const float* __restrict__ b2,
           const float* __restrict__ m2, const float* __restrict__ v2) {
    int tid = threadIdx.x;
    int wid = tid >> 5, lid = tid & 31;
    int g = lid >> 2, tig = lid & 3;
    int wm = wid & 3, wn = wid >> 2;
    int b = blockIdx.x;

    char* sExp = dsm + C2_EXP;                 // [208][80] s8 (196 real rows, 64B data/row)
    char* sB   = dsm + C2_B;                   // [64][592] s8
    unsigned char* sRowA = (unsigned char*)(dsm + C2_ROW);
    u32* lut = (u32*)(dsm + C2_LUT);
    float* sMean  = (float*)(dsm + C2_BN);
    float* sScale = (float*)(dsm + C2_BN + 256);
    float* sBias  = (float*)(dsm + C2_BN + 512);

    // B tile: 64 rows x 576 bytes = 2304 cpa16
    #pragma unroll
    for (int i = 0; i < 9; i++) {
        int sg = tid * 9 + i;
        int row = sg / 36, q = sg % 36;
        cpa16(sB + row * 592 + q * 16, g_w2s8 + row * 576 + q * 16);
    }
    CPA_COMMIT();

    if (tid < 16) {
        lut[tid] = ((tid & 1) ? 0x01u : 0xFFu)
                 | (((tid >> 1) & 1) ? 0x0100u : 0xFF00u)
                 | (((tid >> 2) & 1) ? 0x010000u : 0xFF0000u)
                 | (((tid >> 3) & 1) ? 0x01000000u : 0xFF000000u);
    }
    if (tid >= 64 && tid < 128) {
        int c = tid - 64;
        sMean[c]  = m2[c];
        sScale[c] = g2[c] * (1.0f / sqrtf(v2[c] + 1e-5f));
        sBias[c]  = b2[c];
    }
    __syncthreads();   // lut visible

    // expand act1 bits -> s8 rows (stride 80)
    if (tid < 196) {
        u64 w = g_act1[b * 196 + tid];
        u32* dst = (u32*)(sExp + tid * 80);
        #pragma unroll
        for (int j = 0; j < 16; j++)
            dst[j] = lut[(w >> (4 * j)) & 15];
    }
    // im2col row map (replicate clamp)
    for (int i = tid; i < 9 * 208; i += 256) {
        int tap = i / 208, p = i - tap * 208;
        int pos = p < 196 ? p : 195;
        int y = pos / 14, x = pos % 14;
        int dy = tap / 3 - 1, dx = tap % 3 - 1;
        int yy = min(max(y + dy, 0), 13);
        int xx = min(max(x + dx, 0), 13);
        sRowA[i] = (unsigned char)(yy * 14 + xx);
    }
    CPA_WAIT0();
    __syncthreads();

    // shared-space base addresses for ldmatrix
    u32 sExpA = (u32)__cvta_generic_to_shared(sExp);
    u32 sBA   = (u32)__cvta_generic_to_shared(sB);

    // ldmatrix lane mapping
    int rowInTile = (((lid >> 3) & 1) << 3) + (lid & 7);  // matrices 0/2: rows 0-7, 1/3: rows 8-15
    u32 aExtra = ((lid >> 4) & 1) * 16;                   // matrices 2,3: +16 bytes
    int bRow   = lid & 7;                                 // x2: lanes 0-7 matrix0, 8-15 matrix1
    u32 bExtra = ((lid >> 3) & 1) * 16;

    int acc[4][4][4];
    #pragma unroll
    for (int a = 0; a < 4; a++)
        #pragma unroll
        for (int n = 0; n < 4; n++)
            #pragma unroll
            for (int q = 0; q < 4; q++) acc[a][n][q] = 0;

    int nm = (wm == 0) ? 4 : 3;    // m-tiles: wm, wm+4, wm+8 (+12 for wm==0)

    #pragma unroll
    for (int tap = 0; tap < 9; tap++) {
        u32 aAddr[4];
        #pragma unroll
        for (int mi = 0; mi < 4; mi++) {
            if (mi < nm) {
                int base = (wm + 4 * mi) * 16;
                int r = sRowA[tap * 208 + base + rowInTile];
                aAddr[mi] = sExpA + (u32)(r * 80) + aExtra;
            }
        }
        u32 bAddr[4];
        #pragma unroll
        for (int ni = 0; ni < 4; ni++) {
            int rb = wn * 32 + ni * 8 + bRow;
            bAddr[ni] = sBA + (u32)(rb * 592 + tap * 64) + bExtra;
        }
        #pragma unroll
        for (int ks = 0; ks < 2; ks++) {
            u32 af[4][4];
            #pragma unroll
            for (int mi = 0; mi < 4; mi++)
                if (mi < nm) ldm_x4(af[mi], aAddr[mi] + ks * 32);
            u32 bf[4][2];
            #pragma unroll
            for (int ni = 0; ni < 4; ni++)
                ldm_x2(bf[ni], bAddr[ni] + ks * 32);
            #pragma unroll
            for (int mi = 0; mi < 4; mi++)
                if (mi < nm)
                    #pragma unroll
                    for (int ni = 0; ni < 4; ni++)
                        imma16832(acc[mi][ni], af[mi], bf[ni]);
        }
    }
    __syncthreads();   // all mma reads done before smem overlay

    // stage sums [196][64] s32 (overlay over sExp+sB region)
    int* sums = (int*)dsm;
    #pragma unroll
    for (int mi = 0; mi < 4; mi++) {
        if (mi < nm) {
            #pragma unroll
            for (int ni = 0; ni < 4; ni++) {
                int mrow0 = (wm + 4 * mi) * 16 + g;
                int mrow1 = mrow0 + 8;
                int c0 = wn * 32 + ni * 8 + tig * 2;
                if (mrow0 < 196) *(int2*)(sums + mrow0 * 64 + c0) = make_int2(acc[mi][ni][0], acc[mi][ni][1]);
                if (mrow1 < 196) *(int2*)(sums + mrow1 * 64 + c0) = make_int2(acc[mi][ni][2], acc[mi][ni][3]);
            }
        }
    }
    __syncthreads();

    // maxpool 2x2 (monotone select) + BN + sign -> byte mask
    u64* sPool = (u64*)(dsm + C2_POOL);
    for (int t = tid; t < 392; t += 256) {
        int p = t >> 3, cs = t & 7;
        int py = p / 7, px = p % 7;
        int b00 = ((py * 2) * 14 + px * 2) * 64;
        int b01 = b00 + 64, b10 = b00 + 14 * 64, b11 = b10 + 64;
        u32 msk = 0;
        #pragma unroll
        for (int j = 0; j < 8; j++) {
            int c = cs * 8 + j;
            int s00 = sums[b00 + c], s01 = sums[b01 + c];
            int s10 = sums[b10 + c], s11 = sums[b11 + c];
            int mx = max(max(s00, s01), max(s10, s11));
            int mn = min(min(s00, s01), min(s10, s11));
            float s = sScale[c];
            int sel = (s >= 0.f) ? mx : mn;
            if (((float)sel - sMean[c]) * s + sBias[c] >= 0.f) msk |= 1u << j;
        }
        ((unsigned char*)sPool)[p * 8 + cs] = (unsigned char)msk;
    }
    __syncthreads();

    // emit s8 A row for fc1: A[b][ch*49+p]
    for (int t = tid; t < 392; t += 256) {
        int e0 = t * 8;
        u32 w0 = 0, w1 = 0;
        #pragma unroll
        for (int i = 0; i < 4; i++) {
            int e = e0 + i;
            int ch = e / 49, pp = e - ch * 49;
            w0 |= (((sPool[pp] >> ch) & 1) ? 0x01u : 0xFFu) << (i * 8);
        }
        #pragma unroll
        for (int i = 0; i < 4; i++) {
            int e = e0 + 4 + i;
            int ch = e / 49, pp = e - ch * 49;
            w1 |= (((sPool[pp] >> ch) & 1) ? 0x01u : 0xFFu) << (i * 8);
        }
        *(uint2*)(g_act2s8 + (size_t)b * 3136 + e0) = make_uint2(w0, w1);
    }
}

// ---------------- stage 3: fc1 = s8 mma GEMM (R13: 4-stage pipeline, 128 CTAs) ----------------
static constexpr int F1_STAGE = 20480;          // A[128][80] + B[128][80]
static constexpr int F1_BN    = 4 * F1_STAGE;   // 81920
static constexpr int F1_SMEM  = F1_BN + 3 * 128 * 4;   // 83456

extern __shared__ __align__(16) char f1sm[];
__global__ void __launch_bounds__(256, 1)
k_fc1mma(const float* __restrict__ g3, const float* __restrict__ b3,
         const float* __restrict__ m3, const float* __restrict__ v3) {
    int tid = threadIdx.x;
    int wid = tid >> 5, lid = tid & 31;
    int g = lid >> 2, tig = lid & 3;
    int wm = wid & 3, wn = wid >> 2;       // 4 warps M, 2 warps N
    int nt = blockIdx.x, mt = blockIdx.y;

    float* sMean  = (float*)(f1sm + F1_BN);
    float* sScale = (float*)(f1sm + F1_BN + 512);
    float* sBias  = (float*)(f1sm + F1_BN + 1024);

    const char* gA = g_act2s8 + (size_t)mt * 128 * 3136;
    const char* gB = g_fc1s8 + (size_t)nt * 128 * 3136;

    if (tid < 128) {
        int j = nt * 128 + tid;
        sMean[tid]  = m3[j];
        sScale[tid] = g3[j] * (1.0f / sqrtf(v3[j] + 1e-5f));
        sBias[tid]  = b3[j];
    }

    auto load_chunk = [&](int c) {
        char* As = f1sm + (c & 3) * F1_STAGE;
        char* Bs = As + 10240;
        const char* gAc = gA + c * 64;
        const char* gBc = gB + c * 64;
        #pragma unroll
        for (int i = 0; i < 4; i++) {
            int sg = tid * 4 + i;             // 0..1023
            int row = (sg >> 2) & 127;
            int q = sg & 3;
            bool isB = sg >= 512;
            const char* src = (isB ? gBc : gAc) + (size_t)row * 3136 + q * 16;
            char* dst = (isB ? Bs : As) + row * 80 + q * 16;
            cpa16(dst, src);
        }
        CPA_COMMIT();
    };

    int acc[2][8][4];
    #pragma unroll
    for (int mi = 0; mi < 2; mi++)
        #pragma unroll
        for (int ni = 0; ni < 8; ni++)
            #pragma unroll
            for (int q = 0; q < 4; q++) acc[mi][ni][q] = 0;

    load_chunk(0); load_chunk(1);
    for (int c = 0; c < 49; c++) {
        if (c + 2 < 49) { load_chunk(c + 2); CPA_WAIT2(); }
        else if (c + 1 < 49) { CPA_WAIT1(); }
        else { CPA_WAIT0(); }
        __syncthreads();

        const char* As = f1sm + (c & 3) * F1_STAGE;
        const char* Bs = As + 10240;
        #pragma unroll
        for (int ks = 0; ks < 2; ks++) {
            int kb = ks * 32 + tig * 4;
            u32 af[2][4];
            #pragma unroll
            for (int mi = 0; mi < 2; mi++) {
                int r = wm * 32 + mi * 16 + g;
                af[mi][0] = *(const u32*)(As + r * 80 + kb);
                af[mi][1] = *(const u32*)(As + (r + 8) * 80 + kb);
                af[mi][2] = *(const u32*)(As + r * 80 + kb + 16);
                af[mi][3] = *(const u32*)(As + (r + 8) * 80 + kb + 16);
            }
            u32 bf[8][2];
            #pragma unroll
            for (int ni = 0; ni < 8; ni++) {
                int r = wn * 64 + ni * 8 + g;
                bf[ni][0] = *(const u32*)(Bs + r * 80 + kb);
                bf[ni][1] = *(const u32*)(Bs + r * 80 + kb + 16);
            }
            #pragma unroll
            for (int mi = 0; mi < 2; mi++)
                #pragma unroll
                for (int ni = 0; ni < 8; ni++)
                    imma16832(acc[mi][ni], af[mi], bf[ni]);
        }
    }
    __syncthreads();   // all reads done before smem reuse

    // epilogue: BN + sign -> byte stage (per-warp [32][64]) -> packed u32 words
    char* bw = f1sm + wid * 2048;
    #pragma unroll
    for (int mi = 0; mi < 2; mi++) {
        #pragma unroll
        for (int ni = 0; ni < 8; ni++) {
            int cc0 = ni * 8 + tig * 2;
            int jj0 = wn * 64 + cc0;
            float m0 = sMean[jj0], s0 = sScale[jj0], bb0 = sBias[jj0];
            float m1 = sMean[jj0 + 1], s1 = sScale[jj0 + 1], bb1 = sBias[jj0 + 1];
            int r0 = mi * 16 + g, r1 = r0 + 8;
            bw[r0 * 64 + cc0]     = (((float)acc[mi][ni][0] - m0) * s0 + bb0 >= 0.f);
            bw[r0 * 64 + cc0 + 1] = (((float)acc[mi][ni][1] - m1) * s1 + bb1 >= 0.f);
            bw[r1 * 64 + cc0]     = (((float)acc[mi][ni][2] - m0) * s0 + bb0 >= 0.f);
            bw[r1 * 64 + cc0 + 1] = (((float)acc[mi][ni][3] - m1) * s1 + bb1 >= 0.f);
        }
    }
    __syncwarp();
    {
        int r = lid;
        const u32* bu = (const u32*)(bw + r * 64);
        u32 w0 = 0, w1 = 0;
        #pragma unroll
        for (int q = 0; q < 8; q++) {
            u32 v = bu[q];
            w0 |= ((v & 1u) << (q * 4)) | (((v >> 8) & 1u) << (q * 4 + 1))
                | (((v >> 16) & 1u) << (q * 4 + 2)) | (((v >> 24) & 1u) << (q * 4 + 3));
        }
        #pragma unroll
        for (int q = 0; q < 8; q++) {
            u32 v = bu[8 + q];
            w1 |= ((v & 1u) << (q * 4)) | (((v >> 8) & 1u) << (q * 4 + 1))
                | (((v >> 16) & 1u) << (q * 4 + 2)) | (((v >> 24) & 1u) << (q * 4 + 3));
        }
        int m = mt * 128 + wm * 32 + r;
        g_act3[(size_t)m * 64 + nt * 4 + wn * 2]     = w0;
        g_act3[(size_t)m * 64 + nt * 4 + wn * 2 + 1] = w1;
    }
}

// ---------------- stage 4: fc2 + scale ----------------
__global__ void k_fc2(const float* __restrict__ scale, float* __restrict__ out) {
    int idx = blockIdx.x * blockDim.x + threadIdx.x;   // 40960
    if (idx >= 40960) return;
    int q = idx & 3;
    int rest = idx >> 2;
    int s = rest / 10, o = rest % 10;
    const uint4* a = (const uint4*)(g_act3 + s * 64) + q * 4;
    const uint4* w = (const uint4*)(g_fc2b + o * 64) + q * 4;
    int d = 0;
    #pragma unroll
    for (int k = 0; k < 4; k++) {
        uint4 av = a[k], wv = w[k];
        d += __popc(av.x ^ wv.x) + __popc(av.y ^ wv.y)
           + __popc(av.z ^ wv.z) + __popc(av.w ^ wv.w);
    }
    d += __shfl_xor_sync(0xffffffffu, d, 1);
    d += __shfl_xor_sync(0xffffffffu, d, 2);
    if (q == 0) out[s * 10 + o] = (float)(2048 - 2 * d) * scale[0];
}

// ---------------- launch ----------------
extern "C" void kernel_launch(void* const* d_in, const int* in_sizes, int n_in,
                              void* d_out, int out_size) {
    const float* x       = (const float*)d_in[0];
    const float* conv1_w = (const float*)d_in[1];
    const float* bn1_g   = (const float*)d_in[2];
    const float* bn1_b   = (const float*)d_in[3];
    const float* bn1_m   = (const float*)d_in[4];
    const float* bn1_v   = (const float*)d_in[5];
    const float* conv2_w = (const float*)d_in[6];
    const float* bn2_g   = (const float*)d_in[7];
    const float* bn2_b   = (const float*)d_in[8];
    const float* bn2_m   = (const float*)d_in[9];
    const float* bn2_v   = (const float*)d_in[10];
    const float* fc1_w   = (const float*)d_in[11];
    const float* bn3_g   = (const float*)d_in[12];
    const float* bn3_b   = (const float*)d_in[13];
    const float* bn3_m   = (const float*)d_in[14];
    const float* bn3_v   = (const float*)d_in[15];
    const float* fc2_w   = (const float*)d_in[16];
    const float* scale   = (const float*)d_in[17];
    float* out = (float*)d_out;

    // #0: conv1 + fc1 s8 weight convert + conv2 s8 weight expand
    k_front<<<2049, 416>>>(x, conv1_w, bn1_g, bn1_b, bn1_m, bn1_v,
                           conv2_w, fc1_w);
    // #1,#2: tiny fillers -> conv2mma lands at captured idx 3
    k_packfc2a<<<2, 192>>>(fc2_w);
    k_packfc2b<<<2, 192>>>(fc2_w);
    // #3: conv2 tensor-core with ldmatrix (profiled)
    cudaFuncSetAttribute(k_conv2mma, cudaFuncAttributeMaxDynamicSharedMemorySize, C2_SMEM);
    k_conv2mma<<<1024, 256, C2_SMEM>>>(bn2_g, bn2_b, bn2_m, bn2_v);
    // #4: fc1 tensor-core GEMM (R13 config)
    cudaFuncSetAttribute(k_fc1mma, cudaFuncAttributeMaxDynamicSharedMemorySize, F1_SMEM);
    {
        dim3 grid(16, 8);
        k_fc1mma<<<grid, 256, F1_SMEM>>>(bn3_g, bn3_b, bn3_m, bn3_v);
    }
    // #5
    k_fc2<<<160, 256>>>(scale, out);
}